// round 17
// baseline (speedup 1.0000x reference)
#include <cuda_runtime.h>
#include <cstdint>

#define N_ROWS 65536
#define DIM    256
#define K_CODES 1024
#define MARGIN 2e-3f
#define NCAND  32

// ================= scratch (no allocations allowed) =================
__device__ uint4 g_A8[N_ROWS * DIM / 16];      // int8 z, A-frag-linearized (m16n8k32)
__device__ uint4 g_B8[K_CODES * DIM / 16];     // int8 e, B-frag-linearized
__device__ float g_eT[K_CODES * DIM];          // transposed codebook [k][d] fp32
__device__ float g_a[N_ROWS];                  // ||z_row||^2 (exact replication)
__device__ float2 g_bse[K_CODES];              // (||e_k||^2, int8 scale se_k)
__device__ float g_sza[N_ROWS];                // per-row int8 scale
__device__ int   g_idx[N_ROWS];
__device__ int   g_hist[K_CODES];
__device__ float g_part[N_ROWS / 8];

// ================= helpers =================
__device__ __forceinline__ uint32_t smem_u32(const void* p) {
    uint32_t a;
    asm("{ .reg .u64 t; cvta.to.shared.u64 t, %1; cvt.u32.u64 %0, t; }" : "=r"(a) : "l"(p));
    return a;
}
__device__ __forceinline__ void cp16(uint32_t dst, const void* src) {
    asm volatile("cp.async.cg.shared.global [%0], [%1], 16;" :: "r"(dst), "l"(src));
}
__device__ __forceinline__ void imma32(int* c, const uint4& a, const uint2& b) {
    asm("mma.sync.aligned.m16n8k32.row.col.s32.s8.s8.s32 "
        "{%0,%1,%2,%3}, {%4,%5,%6,%7}, {%8,%9}, {%0,%1,%2,%3};"
        : "+r"(c[0]), "+r"(c[1]), "+r"(c[2]), "+r"(c[3])
        : "r"(a.x), "r"(a.y), "r"(a.z), "r"(a.w), "r"(b.x), "r"(b.y));
}
__device__ __forceinline__ uint32_t fmap(float f) {
    uint32_t u = __float_as_uint(f);
    return (u >> 31) ? ~u : (u | 0x80000000u);
}
__device__ __forceinline__ float funmap(uint32_t u) {
    return __uint_as_float((u >> 31) ? (u & 0x7fffffffu) : ~u);
}
__device__ __forceinline__ uint32_t q4pack(const float* zrow, int k, float rs) {
    uint32_t r = 0;
    #pragma unroll
    for (int b = 0; b < 4; b++) {
        int q = __float2int_rn(zrow[k + b] * rs);
        q = max(-127, min(127, q));
        r |= ((uint32_t)q & 0xFFu) << (b * 8);
    }
    return r;
}

// ---------- prepass A: z -> int8 (per-row scale), A-frag order; exact ||z||^2 ----------
// m16n8k32 A frag: reg0=(g, 4q+b) reg1=(g+8, 4q+b) reg2=(g, 16+4q+b) reg3=(g+8, 16+4q+b)
// tile t=(row>>4)*8+(d>>5); uint4 index = t*32 + lane
__global__ void __launch_bounds__(256) prepA_kernel(const float* __restrict__ z) {
    __shared__ float zs[32 * 260];
    __shared__ float srz[32];
    int tid = threadIdx.x;
    const float4* src = reinterpret_cast<const float4*>(z + (size_t)blockIdx.x * 32 * DIM);
    #pragma unroll
    for (int i = 0; i < 8; i++) {
        int gi = tid + i * 256;
        int row = gi >> 6, c4 = gi & 63;
        *reinterpret_cast<float4*>(&zs[row * 260 + c4 * 4]) = src[gi];
    }
    __syncthreads();
    if (tid < 32) {   // exact sequential square-then-add + row max
        float s = 0.f, mx = 0.f;
        for (int d = 0; d < DIM; d++) {
            float v = zs[tid * 260 + d];
            s = __fadd_rn(s, __fmul_rn(v, v));
            mx = fmaxf(mx, fabsf(v));
        }
        g_a[(size_t)blockIdx.x * 32 + tid] = s;
        float sz = (mx > 0.f) ? mx * (1.0f / 127.0f) : 1.0f;
        g_sza[(size_t)blockIdx.x * 32 + tid] = sz;
        srz[tid] = 1.0f / sz;
    }
    __syncthreads();
    uint4* outp = g_A8 + (size_t)blockIdx.x * 512;
    #pragma unroll
    for (int i = 0; i < 2; i++) {
        int f = tid + i * 256;               // uint4 id 0..511 in this 32-row block
        int tile = f >> 5, r = f & 31;
        int mt = tile >> 3, kt = tile & 7;
        int g = r >> 2, q = r & 3;
        int row0 = mt * 16 + g, row1 = row0 + 8;
        int k0 = kt * 32 + q * 4;
        uint4 w;
        w.x = q4pack(&zs[row0 * 260], k0,      srz[row0]);
        w.y = q4pack(&zs[row1 * 260], k0,      srz[row1]);
        w.z = q4pack(&zs[row0 * 260], k0 + 16, srz[row0]);
        w.w = q4pack(&zs[row1 * 260], k0 + 16, srz[row1]);
        outp[f] = w;
    }
}

// ---------- prepass B: e^T, (||e_k||^2, se_k), int8 B-frag order, hist zero ----------
// B frag: reg0=(4q+b, g) reg1=(16+4q+b, g); tile u=(code>>3)*8+(d>>5), 256B/tile
__global__ void __launch_bounds__(256) prepB_kernel(const float* __restrict__ e) {
    int k = blockIdx.x;       // code
    int d = threadIdx.x;      // dim
    float v = e[(size_t)d * K_CODES + k];
    g_eT[k * DIM + d] = v;

    __shared__ float red[256], redm[256];
    red[d] = __fmul_rn(v, v);
    redm[d] = fabsf(v);
    __syncthreads();
    #pragma unroll
    for (int off = 128; off > 0; off >>= 1) {
        if (d < off) {
            red[d] = __fadd_rn(red[d], red[d + off]);
            redm[d] = fmaxf(redm[d], redm[d + off]);
        }
        __syncthreads();
    }
    float mx = redm[0];
    float se = (mx > 0.f) ? mx * (1.0f / 127.0f) : 1.0f;
    if (d == 0) g_bse[k] = make_float2(red[0], se);
    if (blockIdx.x < 4) g_hist[blockIdx.x * 256 + d] = 0;

    int q = __float2int_rn(v * (1.0f / se));
    q = max(-127, min(127, q));
    int dd = d & 31;
    int reg = dd >> 4, qq = (dd & 15) >> 2, b = dd & 3;
    int lane = (k & 7) * 4 + qq;
    int u = (k >> 3) * 8 + (d >> 5);
    reinterpret_cast<uint8_t*>(g_B8)[(size_t)u * 256 + lane * 8 + reg * 4 + b] = (uint8_t)(q & 0xFF);
}

// ---------- main filter GEMM (s8 IMMA m16n8k32) + lossless shortlist + exact refine ----------
// CTA: 128 rows x all 1024 codes, 256 threads = 8 warps (4m x 2n), warp tile 32x64.
// 8 pipeline iterations (one per 128-code block, full K=256 per B chunk).
// smem u32: A[8192]@0 | B 2st x 8192 @8192 | row_min[128]@24576 | cnt[128]@24704 |
//           cand u16[128*32] @24832 (2048 u32) | ovf @26880 (132 u32) -> 27012 u32 = 108048 B
#define SM_B    8192
#define SM_RMIN 24576
#define SM_CNT  24704
#define SM_CAND 24832
#define SM_OVF  26880
#define GEMM_SMEM_BYTES (27012 * 4)

__global__ void __launch_bounds__(256, 2) gemm_argmin_kernel(const float* __restrict__ z) {
    extern __shared__ __align__(16) uint32_t s32[];
    int tid = threadIdx.x, lane = tid & 31, wid = tid >> 5;
    int warp_m = wid & 3, warp_n = wid >> 2;
    int rblk = blockIdx.x;
    uint32_t* row_min = s32 + SM_RMIN;
    int* cnt = reinterpret_cast<int*>(s32 + SM_CNT);
    unsigned short* cand = reinterpret_cast<unsigned short*>(s32 + SM_CAND);
    int* ovf_cnt = reinterpret_cast<int*>(s32 + SM_OVF);
    int* ovf_list = reinterpret_cast<int*>(s32 + SM_OVF + 1);
    uint32_t sbase = smem_u32(s32);

    if (tid < 128) { row_min[tid] = 0xFFFFFFFFu; cnt[tid] = 0; }
    if (tid == 0) *ovf_cnt = 0;

    // A resident: 2048 uint4 = 32KB, frag-linearized contiguous slice
    {
        const uint4* srcA = g_A8 + (size_t)rblk * 2048;
        #pragma unroll
        for (int i = 0; i < 8; i++) {
            int f = tid + i * 256;
            cp16(sbase + (uint32_t)f * 16, srcA + f);
        }
    }
    // B chunk = one 128-code block, full K: 2048 uint4 = 32KB
    auto loadB = [&](int i) {
        int st = i & 1;
        const uint4* srcB = g_B8 + (size_t)i * 2048;
        #pragma unroll
        for (int it = 0; it < 8; it++) {
            int f = tid + it * 256;
            cp16(sbase + (uint32_t)(SM_B + st * 8192) * 4 + (uint32_t)f * 16, srcB + f);
        }
        asm volatile("cp.async.commit_group;" ::: "memory");
    };
    loadB(0);    // group 0 (includes A)
    loadB(1);    // group 1

    int g = lane >> 2, q2 = (lane & 3) * 2;
    int rowbase = rblk * 128;
    float sza[2][2];
    #pragma unroll
    for (int m = 0; m < 2; m++) {
        int r0 = warp_m * 32 + m * 16 + g;
        sza[m][0] = __ldg(g_sza + rowbase + r0);
        sza[m][1] = __ldg(g_sza + rowbase + r0 + 8);
    }

    int acc[2][8][4];

    for (int nb = 0; nb < 8; nb++) {
        if (nb < 7) asm volatile("cp.async.wait_group 1;" ::: "memory");
        else        asm volatile("cp.async.wait_group 0;" ::: "memory");
        __syncthreads();

        #pragma unroll
        for (int m = 0; m < 2; m++)
            #pragma unroll
            for (int n = 0; n < 8; n++)
                #pragma unroll
                for (int j = 0; j < 4; j++) acc[m][n][j] = 0;

        int st = nb & 1;
        #pragma unroll
        for (int kt = 0; kt < 8; kt++) {
            uint4 av[2];
            #pragma unroll
            for (int m = 0; m < 2; m++)
                av[m] = *reinterpret_cast<const uint4*>(
                    &s32[((warp_m * 2 + m) * 8 + kt) * 128 + lane * 4]);
            uint2 bv[8];
            #pragma unroll
            for (int n = 0; n < 8; n++)
                bv[n] = *reinterpret_cast<const uint2*>(
                    &s32[SM_B + st * 8192 + ((warp_n * 8 + n) * 8 + kt) * 64 + lane * 2]);
            #pragma unroll
            for (int m = 0; m < 2; m++)
                #pragma unroll
                for (int n = 0; n < 8; n++) imma32(acc[m][n], av[m], bv[n]);
        }

        // phase 1: per-row running min of d = b - 2*sza*se*dot
        #pragma unroll
        for (int m = 0; m < 2; m++) {
            float mn0 = __int_as_float(0x7f800000), mn1 = mn0;
            #pragma unroll
            for (int n = 0; n < 8; n++) {
                int code = nb * 128 + warp_n * 64 + n * 8 + q2;
                float2 bs0 = __ldg(&g_bse[code]), bs1 = __ldg(&g_bse[code + 1]);
                float d00 = fmaf((float)acc[m][n][0], -2.f * sza[m][0] * bs0.y, bs0.x);
                float d01 = fmaf((float)acc[m][n][1], -2.f * sza[m][0] * bs1.y, bs1.x);
                float d10 = fmaf((float)acc[m][n][2], -2.f * sza[m][1] * bs0.y, bs0.x);
                float d11 = fmaf((float)acc[m][n][3], -2.f * sza[m][1] * bs1.y, bs1.x);
                mn0 = fminf(mn0, fminf(d00, d01));
                mn1 = fminf(mn1, fminf(d10, d11));
            }
            #pragma unroll
            for (int off = 1; off <= 2; off <<= 1) {
                mn0 = fminf(mn0, __shfl_xor_sync(0xffffffffu, mn0, off));
                mn1 = fminf(mn1, __shfl_xor_sync(0xffffffffu, mn1, off));
            }
            if ((lane & 3) == 0) {
                int r0 = warp_m * 32 + m * 16 + g;
                atomicMin(&row_min[r0], fmap(mn0));
                atomicMin(&row_min[r0 + 8], fmap(mn1));
            }
        }
        __syncthreads();
        if (nb < 6) loadB(nb + 2);   // stage nb&1 fully consumed

        // phase 2: collect candidates within margin (overflow handled later)
        #pragma unroll
        for (int m = 0; m < 2; m++) {
            int r0 = warp_m * 32 + m * 16 + g, r1 = r0 + 8;
            float t0 = funmap(row_min[r0]) + MARGIN;
            float t1 = funmap(row_min[r1]) + MARGIN;
            #pragma unroll
            for (int n = 0; n < 8; n++) {
                int code = nb * 128 + warp_n * 64 + n * 8 + q2;
                float2 bs0 = __ldg(&g_bse[code]), bs1 = __ldg(&g_bse[code + 1]);
                float d00 = fmaf((float)acc[m][n][0], -2.f * sza[m][0] * bs0.y, bs0.x);
                float d01 = fmaf((float)acc[m][n][1], -2.f * sza[m][0] * bs1.y, bs1.x);
                float d10 = fmaf((float)acc[m][n][2], -2.f * sza[m][1] * bs0.y, bs0.x);
                float d11 = fmaf((float)acc[m][n][3], -2.f * sza[m][1] * bs1.y, bs1.x);
                if (d00 <= t0) { int p = atomicAdd(&cnt[r0], 1); if (p < NCAND) cand[r0 * NCAND + p] = (unsigned short)code; }
                if (d01 <= t0) { int p = atomicAdd(&cnt[r0], 1); if (p < NCAND) cand[r0 * NCAND + p] = (unsigned short)(code + 1); }
                if (d10 <= t1) { int p = atomicAdd(&cnt[r1], 1); if (p < NCAND) cand[r1 * NCAND + p] = (unsigned short)code; }
                if (d11 <= t1) { int p = atomicAdd(&cnt[r1], 1); if (p < NCAND) cand[r1 * NCAND + p] = (unsigned short)(code + 1); }
            }
        }
    }
    __syncthreads();

    // ---- exact refine: R2-identical numerics (sequential FMA, fl(fl(a+b)-2m)) ----
    if (tid < 128) {
        int nc = cnt[tid];
        if (nc > NCAND) {
            int p = atomicAdd(ovf_cnt, 1);   // lossless fallback path
            ovf_list[p] = tid;
        } else {
            int row = rowbase + tid;
            float a = g_a[row];
            const float* zr = z + (size_t)row * DIM;
            unsigned long long best = ~0ull;
            for (int ci = 0; ci < nc; ci++) {
                int k = (int)cand[tid * NCAND + ci];
                const float* er = g_eT + (size_t)k * DIM;
                float m = 0.f;
                for (int d = 0; d < DIM; d++) m = __fmaf_rn(zr[d], er[d], m);
                float dist = __fsub_rn(__fadd_rn(a, __ldg(&g_bse[k].x)), 2.0f * m);
                unsigned long long key =
                    ((unsigned long long)__float_as_uint(dist) << 32) | (unsigned)k;
                if (key < best) best = key;
            }
            g_idx[row] = (int)(best & 0xFFFFFFFFull);
        }
    }
    __syncthreads();

    // ---- overflow fallback: block-parallel exact scan of all 1024 codes ----
    int novf = *ovf_cnt;
    for (int oi = 0; oi < novf; oi++) {
        int row = rowbase + ovf_list[oi];
        float* zrow_s = reinterpret_cast<float*>(s32 + SM_CAND);                 // reuse cand
        unsigned long long* keys = reinterpret_cast<unsigned long long*>(s32 + SM_CAND + 256);
        if (tid < 64)
            reinterpret_cast<float4*>(zrow_s)[tid] =
                reinterpret_cast<const float4*>(z + (size_t)row * DIM)[tid];
        __syncthreads();
        float a = g_a[row];
        unsigned long long best = ~0ull;
        #pragma unroll
        for (int kk = 0; kk < 4; kk++) {
            int k = tid + kk * 256;
            const float* er = g_eT + (size_t)k * DIM;
            float m = 0.f;
            for (int d = 0; d < DIM; d++) m = __fmaf_rn(zrow_s[d], er[d], m);
            float dist = __fsub_rn(__fadd_rn(a, __ldg(&g_bse[k].x)), 2.0f * m);
            unsigned long long key =
                ((unsigned long long)__float_as_uint(dist) << 32) | (unsigned)k;
            if (key < best) best = key;
        }
        keys[tid] = best;
        __syncthreads();
        for (int off = 128; off > 0; off >>= 1) {
            if (tid < off && keys[tid + off] < keys[tid]) keys[tid] = keys[tid + off];
            __syncthreads();
        }
        if (tid == 0) g_idx[row] = (int)(keys[0] & 0xFFFFFFFFull);
        __syncthreads();
    }
}

// ---------------- gather + straight-through + loss partials + hist (float4) ----------------
__global__ void __launch_bounds__(256) gather_kernel(const float* __restrict__ z,
                                                     float* __restrict__ out_q,
                                                     float* __restrict__ out_if,
                                                     int write_q, int write_i) {
    int tid = threadIdx.x;
    int warp = tid >> 5, lane = tid & 31;
    size_t row = (size_t)blockIdx.x * 8 + warp;
    int k = g_idx[row];
    const float4* zr = reinterpret_cast<const float4*>(z + row * DIM);
    const float4* er = reinterpret_cast<const float4*>(g_eT + (size_t)k * DIM);
    float4* oq = reinterpret_cast<float4*>(out_q) + row * 64;

    float sq = 0.f;
    #pragma unroll
    for (int j = 0; j < 2; j++) {
        int i4 = lane + 32 * j;
        float4 zv = zr[i4];
        float4 qv = er[i4];
        float dx = __fsub_rn(qv.x, zv.x), dy = __fsub_rn(qv.y, zv.y);
        float dz = __fsub_rn(qv.z, zv.z), dw = __fsub_rn(qv.w, zv.w);
        if (write_q)
            oq[i4] = make_float4(__fadd_rn(zv.x, dx), __fadd_rn(zv.y, dy),
                                 __fadd_rn(zv.z, dz), __fadd_rn(zv.w, dw));
        sq = __fadd_rn(sq, __fmul_rn(dx, dx));
        sq = __fadd_rn(sq, __fmul_rn(dy, dy));
        sq = __fadd_rn(sq, __fmul_rn(dz, dz));
        sq = __fadd_rn(sq, __fmul_rn(dw, dw));
    }
    #pragma unroll
    for (int o = 16; o > 0; o >>= 1)
        sq = __fadd_rn(sq, __shfl_down_sync(0xffffffffu, sq, o));

    __shared__ float ws[8];
    if (lane == 0) {
        ws[warp] = sq;
        atomicAdd(&g_hist[k], 1);
        if (write_i) out_if[row] = (float)k;
    }
    __syncthreads();
    if (tid == 0) {
        float s = 0.f;
        #pragma unroll
        for (int w = 0; w < 8; w++) s = __fadd_rn(s, ws[w]);
        g_part[blockIdx.x] = s;
    }
}

// ---------------- final reductions ----------------
__global__ void __launch_bounds__(256) final_kernel(float* __restrict__ out_s, int write_s) {
    __shared__ float red[256];
    int tid = threadIdx.x;

    float s = 0.f;
    for (int i = tid; i < N_ROWS / 8; i += 256) s = __fadd_rn(s, g_part[i]);
    red[tid] = s;
    __syncthreads();
    #pragma unroll
    for (int off = 128; off > 0; off >>= 1) {
        if (tid < off) red[tid] = __fadd_rn(red[tid], red[tid + off]);
        __syncthreads();
    }
    float vq = red[0] / 16777216.0f;
    __syncthreads();

    float ps = 0.f;
    for (int i = tid; i < K_CODES; i += 256) {
        float p = (float)g_hist[i] * (1.0f / 65536.0f);
        ps = __fadd_rn(ps, __fmul_rn(p, logf(p + 1e-10f)));
    }
    red[tid] = ps;
    __syncthreads();
    #pragma unroll
    for (int off = 128; off > 0; off >>= 1) {
        if (tid < off) red[tid] = __fadd_rn(red[tid], red[tid + off]);
        __syncthreads();
    }
    if (tid == 0 && write_s) {
        out_s[0] = vq;
        out_s[1] = 0.25f * vq;
        out_s[2] = expf(-red[0]);
    }
}

// ---------------- launch ----------------
extern "C" void kernel_launch(void* const* d_in, const int* in_sizes, int n_in,
                              void* d_out, int out_size) {
    const float* z = (const float*)d_in[0];
    const float* e = (const float*)d_in[1];
    float* out = (float*)d_out;

    const int QN = N_ROWS * DIM;
    int write_q = (out_size >= QN) ? 1 : 0;
    int write_i = (out_size >= QN + N_ROWS) ? 1 : 0;
    int write_s = 0;
    float* out_q  = out;
    float* out_if = out + QN;
    float* out_s  = out;
    if (out_size >= QN + N_ROWS + 3) {
        write_s = 1; out_s = out + QN + N_ROWS;
    } else if (out_size == QN + 3) {
        write_s = 1; out_s = out + QN; write_i = 0;
    }

    cudaFuncSetAttribute(gemm_argmin_kernel,
                         cudaFuncAttributeMaxDynamicSharedMemorySize, GEMM_SMEM_BYTES);

    prepA_kernel<<<N_ROWS / 32, 256>>>(z);
    prepB_kernel<<<K_CODES, 256>>>(e);
    gemm_argmin_kernel<<<N_ROWS / 128, 256, GEMM_SMEM_BYTES>>>(z);
    gather_kernel<<<N_ROWS / 8, 256>>>(z, out_q, out_if, write_q, write_i);
    final_kernel<<<1, 256>>>(out_s, write_s);
}